// round 16
// baseline (speedup 1.0000x reference)
#include <cuda_runtime.h>
#include <cstdint>

// Problem constants (fixed shapes per reference)
#define NB      32
#define NC      64
#define NIN     10475
#define NOUT    2619
#define NNZ     (8 * NOUT)        // 20952
#define GPAIR   4                 // (b,c) pairs per block
#define NPAIR   (NB * NC)         // 2048
#define NBLK    (NPAIR / GPAIR)   // 512
#define THREADS 512
#define ROWS_PT 6                 // ceil(NOUT / THREADS)
#define QSIZE   2619              // quarter width (last quarter = 2618)
#define NQUART  4
#define MAXSLOT 16                // Poisson(2)/row-bucket; P(>=16) ~1e-10, guarded
#define RSTRIDE 2624              // smem floats per pair-row (16B mult, >= QSIZE+3)
#define BUFFLT  (GPAIR * RSTRIDE) // floats per quarter buffer (10496)
#define SMEM_BYTES (2 * BUFFLT * sizeof(float))   // 83,968 B -> 2 CTAs/SM

// Device scratch (zero-init at load; no runtime allocation)
__device__ int      d_cnt4[NQUART * NOUT];            // per-quarter counts
__device__ int2     d_ent4[NQUART * MAXSLOT * NOUT];  // slot-major {local col, val}
__device__ unsigned d_done;

// ---------------- ELL fill, bucketed by column quarter ----------------
__global__ void k_fill(const int* __restrict__ rows,
                       const int* __restrict__ cols,
                       const float* __restrict__ vals) {
    int k = blockIdx.x * blockDim.x + threadIdx.x;
    if (k < NNZ) {
        int r = rows[k];
        int c = cols[k];
        int q = c / QSIZE;                      // 0..3
        int lc = c - q * QSIZE;
        int slot = atomicAdd(&d_cnt4[q * NOUT + r], 1);
        if (slot < MAXSLOT)
            d_ent4[q * (MAXSLOT * NOUT) + slot * NOUT + r] =
                make_int2(lc, __float_as_int(vals[k]));
    }
}

// ---------------- mbarrier helpers ----------------
__device__ __forceinline__ void mbar_init(uint32_t a, unsigned cnt) {
    asm volatile("mbarrier.init.shared.b64 [%0], %1;" :: "r"(a), "r"(cnt) : "memory");
}
__device__ __forceinline__ void mbar_expect_tx(uint32_t a, unsigned bytes) {
    asm volatile("mbarrier.arrive.expect_tx.shared.b64 _, [%0], %1;"
                 :: "r"(a), "r"(bytes) : "memory");
}
__device__ __forceinline__ void mbar_wait(uint32_t a, unsigned parity) {
    asm volatile(
        "{\n\t.reg .pred P;\n"
        "W_%=:\n\t"
        "mbarrier.try_wait.parity.acquire.cta.shared::cta.b64 P, [%0], %1, 0x989680;\n\t"
        "@!P bra W_%=;\n\t}"
        :: "r"(a), "r"(parity) : "memory");
}

// ---------------- TMA bulk staging (issued by tid 0 only) ----------------
// Stage quarter q of this block's 4 x-rows into a planar smem buffer via
// cp.async.bulk (UBLKCP): one instruction per ~10.5 KB row-quarter, no
// register round-trip, fully asynchronous, completion via mbarrier tx count.
// Per-row 16B alignment: copy from aligned-down source; element j of the
// row-quarter lands at bufRow[skew + j], skew = (global float index) & 3.
// The single chip-final row-quarter clamps its bulk size (no OOB read) and
// the <=3 tail floats are scalar-stored before the release-arrive.
__device__ __forceinline__ void tma_stage(const float* __restrict__ x,
                                          int pb, int q,
                                          float* __restrict__ bufG,   // generic ptr
                                          uint32_t bufA,              // smem addr
                                          uint32_t mbarA) {
    const int ncols = (q == NQUART - 1) ? (NIN - (NQUART - 1) * QSIZE) : QSIZE;
    unsigned bytes[GPAIR];
    size_t   gf[GPAIR];
    unsigned skewB[GPAIR];
    unsigned total = 0;

    #pragma unroll
    for (int p = 0; p < GPAIR; p++) {
        gf[p]    = (size_t)(pb + p) * NIN + (size_t)q * QSIZE;
        skewB[p] = (unsigned)(gf[p] & 3) * 4u;
        unsigned want = (unsigned)(ncols * 4) + skewB[p];
        unsigned sz   = (want + 15u) & ~15u;
        // clamp against the end of x (only the chip-final row-quarter hits this)
        size_t avail = ((size_t)NPAIR * NIN) * 4 - (gf[p] * 4 - skewB[p]);
        if ((size_t)sz > avail) {
            unsigned szc = (unsigned)(avail & ~(size_t)15);
            int done = (int)((szc - skewB[p]) >> 2);     // floats already covered
            for (int j = done; j < ncols; j++)           // <=3 scalar tail floats
                bufG[p * RSTRIDE + (skewB[p] >> 2) + j] = x[gf[p] + j];
            sz = szc;
        }
        bytes[p] = sz;
        total += sz;
    }

    mbar_expect_tx(mbarA, total);   // release: orders the scalar tail stores too

    #pragma unroll
    for (int p = 0; p < GPAIR; p++) {
        const char* srcA = (const char*)(x + gf[p]) - skewB[p];
        asm volatile(
            "cp.async.bulk.shared::cluster.global.mbarrier::complete_tx::bytes "
            "[%0], [%1], %2, [%3];"
            :: "r"(bufA + (uint32_t)(p * RSTRIDE * 4)), "l"(srcA),
               "r"(bytes[p]), "r"(mbarA)
            : "memory");
    }
}

// ---------------- Main SpMM kernel ----------------
// GPAIR=4, 512 threads, 2 CTAs/SM. Double-buffered column quarters staged by
// TMA bulk copies (zero per-byte issue cost, true async): compute(q) overlaps
// the hardware copy of q+2. Planar smem rows; gather = 4x LDS.32 per entry.
// Accumulators persist across quarters; output written once, coalesced.
__global__ __launch_bounds__(THREADS, 2)
void k_main(const float* __restrict__ x, float* __restrict__ out) {
    extern __shared__ float smf[];                 // 2 * BUFFLT floats
    __shared__ __align__(8) unsigned long long mbar[2];

    const int tid = threadIdx.x;
    const int pb  = blockIdx.x * GPAIR;

    uint32_t smA   = (uint32_t)__cvta_generic_to_shared(smf);
    uint32_t mbarA = (uint32_t)__cvta_generic_to_shared(mbar);

    if (tid == 0) { mbar_init(mbarA, 1); mbar_init(mbarA + 8, 1); }
    __syncthreads();

    if (tid == 0) {
        tma_stage(x, pb, 0, smf,          smA,               mbarA);
        tma_stage(x, pb, 1, smf + BUFFLT, smA + BUFFLT * 4u, mbarA + 8);
    }

    float4 acc[ROWS_PT];
    #pragma unroll
    for (int i = 0; i < ROWS_PT; i++) acc[i] = make_float4(0.f, 0.f, 0.f, 0.f);

    #pragma unroll 1
    for (int q = 0; q < NQUART; q++) {
        const int b = q & 1;
        mbar_wait(mbarA + 8u * b, (unsigned)((q >> 1) & 1));

        const float* __restrict__ buf = smf + b * BUFFLT;
        int base[GPAIR];
        #pragma unroll
        for (int p = 0; p < GPAIR; p++)
            base[p] = p * RSTRIDE +
                      (int)((((size_t)(pb + p) * NIN) + (size_t)q * QSIZE) & 3);

        const int*  __restrict__ cnt = d_cnt4 + q * NOUT;
        const int2* __restrict__ tbl = d_ent4 + q * (MAXSLOT * NOUT);

        int c[ROWS_PT];
        int cmax = 0;
        #pragma unroll
        for (int i = 0; i < ROWS_PT; i++) {
            int r = tid + i * THREADS;
            c[i] = (r < NOUT) ? min(cnt[r], MAXSLOT) : 0;
            cmax = max(cmax, c[i]);
        }

        for (int k = 0; k < cmax; k++) {
            const int2* __restrict__ ek = tbl + k * NOUT;
            #pragma unroll
            for (int i = 0; i < ROWS_PT; i++) {
                if (k < c[i]) {
                    int2 e = __ldg(ek + tid + i * THREADS);
                    float v = __int_as_float(e.y);
                    acc[i].x = fmaf(v, buf[base[0] + e.x], acc[i].x);
                    acc[i].y = fmaf(v, buf[base[1] + e.x], acc[i].y);
                    acc[i].z = fmaf(v, buf[base[2] + e.x], acc[i].z);
                    acc[i].w = fmaf(v, buf[base[3] + e.x], acc[i].w);
                }
            }
        }
        __syncthreads();   // all reads of buf done before it is restaged

        if (q + 2 < NQUART && tid == 0)
            tma_stage(x, pb, q + 2, smf + b * BUFFLT,
                      smA + (uint32_t)(b * BUFFLT * 4), mbarA + 8u * b);
    }

    // ---- coalesced stores: 4 output streams x 6 rows ----
    float* __restrict__ o0 = out + (size_t)pb * NOUT;
    #pragma unroll
    for (int i = 0; i < ROWS_PT; i++) {
        int r = tid + i * THREADS;
        if (r < NOUT) {
            o0[r]            = acc[i].x;
            o0[NOUT + r]     = acc[i].y;
            o0[2 * NOUT + r] = acc[i].z;
            o0[3 * NOUT + r] = acc[i].w;
        }
    }

    // ---- last finished CTA resets counts for the next graph replay ----
    __shared__ unsigned s_last;
    if (tid == 0) {
        __threadfence();
        s_last = (atomicAdd(&d_done, 1u) == (unsigned)(gridDim.x - 1));
    }
    __syncthreads();
    if (s_last) {
        for (int i = tid; i < NQUART * NOUT; i += THREADS) d_cnt4[i] = 0;
        if (tid == 0) d_done = 0;
    }
}

// ---------------- launch ----------------
extern "C" void kernel_launch(void* const* d_in, const int* in_sizes, int n_in,
                              void* d_out, int out_size) {
    const float* x      = (const float*)d_in[0];
    const int*   M_rows = (const int*)d_in[1];
    const int*   M_cols = (const int*)d_in[2];
    const float* M_vals = (const float*)d_in[3];
    float* out = (float*)d_out;

    (void)in_sizes; (void)n_in; (void)out_size;

    cudaFuncSetAttribute(k_main, cudaFuncAttributeMaxDynamicSharedMemorySize,
                         (int)SMEM_BYTES);

    k_fill<<<(NNZ + 255) / 256, 256>>>(M_rows, M_cols, M_vals);
    k_main<<<NBLK, THREADS, SMEM_BYTES>>>(x, out);
}

// round 17
// speedup vs baseline: 1.2607x; 1.2607x over previous
#include <cuda_runtime.h>
#include <cstdint>

// Problem constants (fixed shapes per reference)
#define NB      32
#define NC      64
#define NIN     10475
#define NOUT    2619
#define NNZ     (8 * NOUT)        // 20952
#define GPAIR   4                 // (b,c) pairs per block
#define NPAIR   (NB * NC)         // 2048
#define NBLK    (NPAIR / GPAIR)   // 512
#define THREADS 512
#define ROWS_PT 6                 // ceil(NOUT / THREADS)
#define MAXSLOT 32                // Poisson(4)/half-row; overflow ~0, guarded
#define HALF    5238              // column split point (ceil(NIN/2))
#define SMCOLS  5240              // padded float4 granules per half
#define SMEM_BYTES (SMCOLS * sizeof(float4))  // 83,840 B -> 2 CTAs/SM

// Device scratch (zero-init at load; no runtime allocation)
__device__ int      d_cntL[NOUT];             // per-half counts; reset each call
__device__ int      d_cntH[NOUT];
__device__ int2     d_entL[MAXSLOT * NOUT];   // slot-major {local col, val-bits}
__device__ int2     d_entH[MAXSLOT * NOUT];
__device__ unsigned d_done;

// ---------------- ELL fill, bucketed by column half ----------------
__global__ void k_fill(const int* __restrict__ rows,
                       const int* __restrict__ cols,
                       const float* __restrict__ vals) {
    int k = blockIdx.x * blockDim.x + threadIdx.x;
    if (k < NNZ) {
        int r = rows[k];
        int c = cols[k];
        int vb = __float_as_int(vals[k]);
        if (c < HALF) {
            int slot = atomicAdd(&d_cntL[r], 1);
            if (slot < MAXSLOT) d_entL[slot * NOUT + r] = make_int2(c, vb);
        } else {
            int slot = atomicAdd(&d_cntH[r], 1);
            if (slot < MAXSLOT) d_entH[slot * NOUT + r] = make_int2(c - HALF, vb);
        }
    }
}

// ---------------- Main SpMM kernel ----------------
// Round-8 structure (GPAIR=4, two column-half phases, 512 thr, 2 CTAs/SM,
// float4-interleaved gather: one LDS.128 per entry serves all 4 pairs)
// + k-loop UNROLL 3: iterations are mutually independent (addresses don't
// depend on loaded data), so unrolling triples entry-load MLP per thread
// (6 -> 18 LDG.64 in flight) and lets the scheduler overlap iteration k's
// LDS/FMA with k+1/k+2's LDGs — attacking the latency-exposure profile
// without touching the proven memory layout.
__global__ __launch_bounds__(THREADS, 2)
void k_main(const float* __restrict__ x, float* __restrict__ out) {
    extern __shared__ float4 sm4[];   // SMCOLS granules
    const int tid = threadIdx.x;
    const int pb  = blockIdx.x * GPAIR;

    float4 acc[ROWS_PT];
    #pragma unroll
    for (int i = 0; i < ROWS_PT; i++) acc[i] = make_float4(0.f, 0.f, 0.f, 0.f);

    #pragma unroll
    for (int h = 0; h < 2; h++) {
        const int ncols = h ? (NIN - HALF) : HALF;
        const float* __restrict__ xh = x + (size_t)pb * NIN + h * HALF;

        // ---- stage this column half: 4 coalesced streams -> STS.128 ----
        for (int j = tid; j < ncols; j += THREADS) {
            sm4[j] = make_float4(__ldg(xh + j),
                                 __ldg(xh + j + NIN),
                                 __ldg(xh + j + 2 * NIN),
                                 __ldg(xh + j + 3 * NIN));
        }
        __syncthreads();

        // ---- accumulate this half's entries: 6 lockstep row-chains ----
        const int*  __restrict__ cnt = h ? d_cntH : d_cntL;
        const int2* __restrict__ tbl = h ? d_entH : d_entL;

        int c[ROWS_PT];
        int cmax = 0;
        #pragma unroll
        for (int i = 0; i < ROWS_PT; i++) {
            int r = tid + i * THREADS;
            c[i] = (r < NOUT) ? min(cnt[r], MAXSLOT) : 0;
            cmax = max(cmax, c[i]);
        }

        #pragma unroll 3
        for (int k = 0; k < cmax; k++) {
            const int2* __restrict__ ek = tbl + k * NOUT;
            #pragma unroll
            for (int i = 0; i < ROWS_PT; i++) {
                if (k < c[i]) {
                    int2 e = __ldg(ek + tid + i * THREADS);
                    float v  = __int_as_float(e.y);
                    float4 xv = sm4[e.x];
                    acc[i].x = fmaf(v, xv.x, acc[i].x);
                    acc[i].y = fmaf(v, xv.y, acc[i].y);
                    acc[i].z = fmaf(v, xv.z, acc[i].z);
                    acc[i].w = fmaf(v, xv.w, acc[i].w);
                }
            }
        }
        __syncthreads();   // smem reused by next half
    }

    // ---- coalesced stores: 4 output streams x 6 rows ----
    float* __restrict__ o0 = out + (size_t)pb * NOUT;
    #pragma unroll
    for (int i = 0; i < ROWS_PT; i++) {
        int r = tid + i * THREADS;
        if (r < NOUT) {
            o0[r]            = acc[i].x;
            o0[NOUT + r]     = acc[i].y;
            o0[2 * NOUT + r] = acc[i].z;
            o0[3 * NOUT + r] = acc[i].w;
        }
    }

    // ---- last finished block resets counts for the next graph replay ----
    __shared__ unsigned s_last;
    if (tid == 0) {
        __threadfence();
        s_last = (atomicAdd(&d_done, 1u) == (unsigned)(gridDim.x - 1));
    }
    __syncthreads();
    if (s_last) {
        for (int i = tid; i < NOUT; i += THREADS) { d_cntL[i] = 0; d_cntH[i] = 0; }
        if (tid == 0) d_done = 0;
    }
}

// ---------------- launch ----------------
extern "C" void kernel_launch(void* const* d_in, const int* in_sizes, int n_in,
                              void* d_out, int out_size) {
    const float* x      = (const float*)d_in[0];
    const int*   M_rows = (const int*)d_in[1];
    const int*   M_cols = (const int*)d_in[2];
    const float* M_vals = (const float*)d_in[3];
    float* out = (float*)d_out;

    (void)in_sizes; (void)n_in; (void)out_size;

    cudaFuncSetAttribute(k_main, cudaFuncAttributeMaxDynamicSharedMemorySize,
                         (int)SMEM_BYTES);

    k_fill<<<(NNZ + 255) / 256, 256>>>(M_rows, M_cols, M_vals);
    k_main<<<NBLK, THREADS, SMEM_BYTES>>>(x, out);
}